// round 15
// baseline (speedup 1.0000x reference)
#include <cuda_runtime.h>
#include <cuda_fp16.h>
#include <math.h>
#include <cstdint>

// ---------------- problem constants ----------------
#define Bc    4
#define Tc    2048
#define Cc    1024
#define Hc    64
#define HSc   16
#define NTOK  (Bc*Tc)            // 8192
#define C4    (Cc/4)             // 256
#define NC    (NTOK*Cc)
#define DM4   128
#define DDEC  64
#define P_SEG 16
#define TSEG  (Tc/P_SEG)         // 128
#define NSEG  (Bc*Hc*P_SEG)      // 4096

// ---------------- scratch ----------------
// fp32
__device__ __align__(16) float g_y  [NC];
__device__ __align__(16) float g_we [NC];
__device__ __align__(16) float g_sseg[NSEG*256];
__device__ __align__(16) float g_wp  [NSEG*16];
// fp16 activations
__device__ __align__(16) __half g16_yn [NC];
__device__ __align__(16) __half g16_xw [NC];
__device__ __align__(16) __half g16_xk [NC];
__device__ __align__(16) __half g16_xv [NC];
__device__ __align__(16) __half g16_xr [NC];
__device__ __align__(16) __half g16_r  [NC];
__device__ __align__(16) __half g16_k  [NC];
__device__ __align__(16) __half g16_v  [NC];
__device__ __align__(16) __half g16_h  [NTOK*DM4];
__device__ __align__(16) __half g16_t1 [NTOK*DDEC];
// fp16 weights
__device__ __align__(16) __half g16_wr [Cc*Cc];
__device__ __align__(16) __half g16_wk [Cc*Cc];
__device__ __align__(16) __half g16_wv [Cc*Cc];
__device__ __align__(16) __half g16_wo [Cc*Cc];
__device__ __align__(16) __half g16_w1 [Cc*DM4];
__device__ __align__(16) __half g16_dw1[Cc*DDEC];
__device__ __align__(16) __half g16_dw2[DDEC*Cc];
__device__ __align__(16) __half g16_w2 [4*32*Cc];

// ---------------- helpers ----------------
__device__ __forceinline__ uint32_t smem_u32(const void* p) {
    uint32_t a;
    asm("{ .reg .u64 t; cvta.to.shared.u64 t, %1; cvt.u32.u64 %0, t; }" : "=r"(a) : "l"(p));
    return a;
}
__device__ __forceinline__ void ldsm4(uint32_t* r, uint32_t addr) {
    asm volatile("ldmatrix.sync.aligned.m8n8.x4.shared.b16 {%0,%1,%2,%3}, [%4];"
        : "=r"(r[0]), "=r"(r[1]), "=r"(r[2]), "=r"(r[3]) : "r"(addr));
}
__device__ __forceinline__ void ldsm4t(uint32_t* r, uint32_t addr) {
    asm volatile("ldmatrix.sync.aligned.m8n8.x4.trans.shared.b16 {%0,%1,%2,%3}, [%4];"
        : "=r"(r[0]), "=r"(r[1]), "=r"(r[2]), "=r"(r[3]) : "r"(addr));
}
__device__ __forceinline__ void mma16816(float* d, const uint32_t* a, const uint32_t* b) {
    asm volatile(
        "mma.sync.aligned.m16n8k16.row.col.f32.f16.f16.f32 "
        "{%0,%1,%2,%3}, {%4,%5,%6,%7}, {%8,%9}, {%0,%1,%2,%3};"
        : "+f"(d[0]), "+f"(d[1]), "+f"(d[2]), "+f"(d[3])
        : "r"(a[0]), "r"(a[1]), "r"(a[2]), "r"(a[3]), "r"(b[0]), "r"(b[1]));
}
__device__ __forceinline__ void cp16(uint32_t sdst, const void* gsrc) {
    asm volatile("cp.async.cg.shared.global [%0], [%1], 16;" :: "r"(sdst), "l"(gsrc));
}
#define CP_COMMIT() asm volatile("cp.async.commit_group;")
#define CP_WAIT1()  asm volatile("cp.async.wait_group 1;")
#define CP_WAIT0()  asm volatile("cp.async.wait_group 0;")

__device__ __forceinline__ uint32_t h2u(float a, float b) {
    __half2 h = __floats2half2_rn(a, b);
    return *reinterpret_cast<uint32_t*>(&h);
}
__device__ __forceinline__ uint2 f4toh(float4 v) {
    return make_uint2(h2u(v.x, v.y), h2u(v.z, v.w));
}

// ---------------- one-shot weight convert (8 segments) ----------------
struct CvtArgs {
    const float4* s[8];
    uint2* d[8];
    int off[9];
};
__global__ void __launch_bounds__(256) k_cvt(CvtArgs a) {
    int i = blockIdx.x * 256 + threadIdx.x;
    if (i >= a.off[8]) return;
#pragma unroll
    for (int sg = 0; sg < 8; sg++) {
        if (i < a.off[sg + 1]) {
            int j = i - a.off[sg];
            a.d[sg][j] = f4toh(a.s[sg][j]);
            return;
        }
    }
}

// ---------------- GEMM: fp16, cp.async 3-stage BK=64, mma.sync ----------------
enum { EPI_NONE = 0, EPI_TANH = 1, EPI_WEXP = 2 };

template<int BM, int BN, int EPI, int OUTH>
struct GemmBody {
    static __device__ __forceinline__ void run(
        const __half* __restrict__ A, const __half* __restrict__ B,
        void* __restrict__ C, int nT, int lda, int ldb, int ldc,
        const float* __restrict__ bias, char* smem,
        int rowBase, int colBase)
    {
        constexpr int BK   = 64;
        constexpr int S    = 3;
        constexpr int ASTR = BK + 8;      // 72
        constexpr int BSTR = BN + 8;
        constexpr int ABYT = BM * ASTR * 2;
        constexpr int BBYT = BK * BSTR * 2;
        constexpr int MFR  = BM / 32;
        constexpr int NFR  = BN / 32;
        constexpr int A_CH = BM * (BK / 8) / 256;
        constexpr int B_CH = BK * (BN / 8) / 256;
        constexpr int ASH  = (BK == 64) ? 3 : 2;
        constexpr int BSH  = (BN == 128) ? 4 : 3;
        constexpr int KH   = BK / 16;

        char* As = smem;
        char* Bs = smem + S * ABYT;

        const int tid  = threadIdx.x;
        const int wid  = tid >> 5;
        const int lane = tid & 31;
        const int warpM = (wid >> 2) * (BM / 2);
        const int warpN = (wid & 3) * (BN / 4);

        const uint32_t aBase = smem_u32(As);
        const uint32_t bBase = smem_u32(Bs);
        const int lrow  = lane & 15;
        const int lhalf = (lane >> 4) * 8;
        const uint32_t aLane = (uint32_t)((warpM + lrow) * ASTR + lhalf) * 2;
        const uint32_t bLane = (uint32_t)(lrow * BSTR + warpN + lhalf) * 2;

        float acc[MFR][NFR][4];
#pragma unroll
        for (int i = 0; i < MFR; i++)
#pragma unroll
            for (int j = 0; j < NFR; j++)
#pragma unroll
                for (int e = 0; e < 4; e++) acc[i][j][e] = 0.f;

        auto issue = [&](int t) {
            const int kt = t * BK;
            const int sb = t % S;
            uint32_t ad = aBase + sb * ABYT;
            uint32_t bd = bBase + sb * BBYT;
#pragma unroll
            for (int i = 0; i < A_CH; i++) {
                int idx = i * 256 + tid;
                int r = idx >> ASH, ch = idx & ((1 << ASH) - 1);
                cp16(ad + (uint32_t)(r * ASTR + ch * 8) * 2,
                     A + (size_t)(rowBase + r) * lda + kt + ch * 8);
            }
#pragma unroll
            for (int i = 0; i < B_CH; i++) {
                int idx = i * 256 + tid;
                int r = idx >> BSH, ch = idx & ((1 << BSH) - 1);
                cp16(bd + (uint32_t)(r * BSTR + ch * 8) * 2,
                     B + (size_t)(kt + r) * ldb + colBase + ch * 8);
            }
        };

#pragma unroll
        for (int s = 0; s < S - 1; ++s) {
            if (s < nT) issue(s);
            CP_COMMIT();
        }

        for (int t = 0; t < nT; ++t) {
            CP_WAIT1();
            __syncthreads();
            if (t + S - 1 < nT) issue(t + S - 1);
            CP_COMMIT();

            const int sb = t % S;
            const uint32_t ad = aBase + sb * ABYT;
            const uint32_t bd = bBase + sb * BBYT;
#pragma unroll
            for (int k16 = 0; k16 < KH; ++k16) {
                uint32_t af[MFR][4];
                uint32_t bf[NFR][2];
#pragma unroll
                for (int mi = 0; mi < MFR; mi++)
                    ldsm4(af[mi], ad + aLane + (uint32_t)(mi * 16 * ASTR + k16 * 16) * 2);
#pragma unroll
                for (int p = 0; p < NFR / 2; p++)
                    ldsm4t(&bf[p * 2][0], bd + bLane + (uint32_t)(k16 * 16 * BSTR + p * 16) * 2);
#pragma unroll
                for (int mi = 0; mi < MFR; mi++)
#pragma unroll
                    for (int ni = 0; ni < NFR; ni++)
                        mma16816(acc[mi][ni], af[mi], bf[ni]);
            }
        }

        // ---- epilogue ----
        const int row0 = rowBase + warpM + (lane >> 2);
        const int col0 = colBase + warpN + (lane & 3) * 2;
#pragma unroll
        for (int mi = 0; mi < MFR; mi++) {
#pragma unroll
            for (int ni = 0; ni < NFR; ni++) {
#pragma unroll
                for (int half = 0; half < 2; half++) {
                    int row = row0 + mi * 16 + half * 8;
                    int col = col0 + ni * 8;
                    float v0 = acc[mi][ni][half * 2 + 0];
                    float v1 = acc[mi][ni][half * 2 + 1];
                    if (EPI == EPI_TANH) {
                        v0 = tanhf(v0); v1 = tanhf(v1);
                    } else if (EPI == EPI_WEXP) {
                        v0 = expf(-expf(bias[col] + v0));
                        v1 = expf(-expf(bias[col + 1] + v1));
                    }
                    if (OUTH) {
                        *(uint32_t*)((__half*)C + (size_t)row * ldc + col) = h2u(v0, v1);
                    } else {
                        float* co = (float*)C + (size_t)row * ldc + col;
                        co[0] = v0; co[1] = v1;
                    }
                }
            }
        }
    }
};

template<int BM, int BN, int EPI, int OUTH>
__global__ void __launch_bounds__(256, 2)
gemmh(const __half* __restrict__ A, const __half* __restrict__ B,
      void* __restrict__ C, int nT, int lda, int ldb, int ldc,
      const float* __restrict__ bias)
{
    extern __shared__ char smem[];
    GemmBody<BM, BN, EPI, OUTH>::run(A, B, C, nT, lda, ldb, ldc, bias, smem,
                                     blockIdx.x * BM, blockIdx.y * BN);
}

// batched: z=0..2 -> r/k/v projections (fp16 out), z=3 -> wexp (fp32 out)
struct BatchArgs {
    const __half* A[4]; const __half* B[4]; void* C[4];
    int nT[4]; int lda[4];
    const float* bias;
};
__global__ void __launch_bounds__(256, 2)
gemmh_batch(BatchArgs args)
{
    extern __shared__ char smem[];
    const int z = blockIdx.z;
    if (z < 3) {
        GemmBody<128, 128, EPI_NONE, 1>::run(args.A[z], args.B[z], args.C[z],
                                             args.nT[z], args.lda[z], Cc, Cc, nullptr, smem,
                                             blockIdx.x * 128, blockIdx.y * 128);
    } else {
        GemmBody<128, 128, EPI_WEXP, 0>::run(args.A[3], args.B[3], args.C[3],
                                             args.nT[3], args.lda[3], Cc, Cc, args.bias, smem,
                                             blockIdx.x * 128, blockIdx.y * 128);
    }
}

// ---------------- fused shift + h-GEMM: h = tanh((x + (xprev - x)*tmx) @ w1) ----------------
// BM=64, BN=64, BK=64; A built on the fly from fp32 x (xxx never materialized).
#define HF_ASTR 72
#define HF_BSTR 72

__global__ void __launch_bounds__(256, 2)
k_hshift(const float* __restrict__ x, const float* __restrict__ tmx,
         const __half* __restrict__ w1h, __half* __restrict__ h16)
{
    __shared__ __half As[2][64 * HF_ASTR];
    __shared__ __half Bs[3][64 * HF_BSTR];

    const int tid  = threadIdx.x;
    const int wid  = tid >> 5;
    const int lane = tid & 31;
    const int warpM = (wid >> 2) * 32;
    const int warpN = (wid & 3) * 16;
    const int rowBase = blockIdx.x * 64;
    const int colBase = blockIdx.y * 64;
    const int nT = Cc / 64;             // 16

    const uint32_t aBase = smem_u32(As);
    const uint32_t bBase = smem_u32(Bs);

    auto issueB = [&](int t) {
        const int kt = t * 64;
        uint32_t bd = bBase + (uint32_t)((t % 3) * 64 * HF_BSTR) * 2;
#pragma unroll
        for (int i = 0; i < 2; i++) {
            int idx = i * 256 + tid;
            int r = idx >> 3, ch = idx & 7;
            cp16(bd + (uint32_t)(r * HF_BSTR + ch * 8) * 2,
                 w1h + (size_t)(kt + r) * DM4 + colBase + ch * 8);
        }
        CP_COMMIT();
    };

    float4 ax[4], ap[4];
    auto loadA = [&](int t) {
        const int kt = t * 64;
#pragma unroll
        for (int i = 0; i < 4; i++) {
            int idx = i * 256 + tid;
            int r = idx >> 4, ch = idx & 15;
            int grow = rowBase + r;
            size_t go = (size_t)grow * Cc + kt + ch * 4;
            ax[i] = *(const float4*)(x + go);
            if ((grow & (Tc - 1)) == 0)
                ap[i] = make_float4(0.f, 0.f, 0.f, 0.f);
            else
                ap[i] = *(const float4*)(x + go - Cc);
        }
    };

    issueB(0);
    issueB(1);
    loadA(0);

    float acc[2][2][4];
#pragma unroll
    for (int i = 0; i < 2; i++)
#pragma unroll
        for (int j = 0; j < 2; j++)
#pragma unroll
            for (int e = 0; e < 4; e++) acc[i][j][e] = 0.f;

    const int lrow  = lane & 15;
    const int lhalf = (lane >> 4) * 8;
    const uint32_t aLane = (uint32_t)((warpM + lrow) * HF_ASTR + lhalf) * 2;
    const uint32_t bLane = (uint32_t)(lrow * HF_BSTR + warpN + lhalf) * 2;

    for (int t = 0; t < nT; ++t) {
        // STS A(t) from regs (shift math identical to old k_shift)
        {
            const int kt = t * 64;
            __half* dst = As[t & 1];
#pragma unroll
            for (int i = 0; i < 4; i++) {
                int idx = i * 256 + tid;
                int r = idx >> 4, ch = idx & 15;
                float4 tm = *(const float4*)(tmx + kt + ch * 4);
                float4 o;
                o.x = fmaf(ap[i].x - ax[i].x, tm.x, ax[i].x);
                o.y = fmaf(ap[i].y - ax[i].y, tm.y, ax[i].y);
                o.z = fmaf(ap[i].z - ax[i].z, tm.z, ax[i].z);
                o.w = fmaf(ap[i].w - ax[i].w, tm.w, ax[i].w);
                *(uint2*)&dst[r * HF_ASTR + ch * 4] = f4toh(o);
            }
        }
        CP_WAIT1();
        __syncthreads();
        if (t + 2 < nT) issueB(t + 2);
        if (t + 1 < nT) loadA(t + 1);

        const uint32_t ad = aBase + (uint32_t)((t & 1) * 64 * HF_ASTR) * 2;
        const uint32_t bd = bBase + (uint32_t)((t % 3) * 64 * HF_BSTR) * 2;
#pragma unroll
        for (int k16 = 0; k16 < 4; ++k16) {
            uint32_t af[2][4];
            uint32_t bf[2][2];
#pragma unroll
            for (int mi = 0; mi < 2; mi++)
                ldsm4(af[mi], ad + aLane + (uint32_t)(mi * 16 * HF_ASTR + k16 * 16) * 2);
            ldsm4t(&bf[0][0], bd + bLane + (uint32_t)(k16 * 16 * HF_BSTR) * 2);
#pragma unroll
            for (int mi = 0; mi < 2; mi++)
#pragma unroll
                for (int ni = 0; ni < 2; ni++)
                    mma16816(acc[mi][ni], af[mi], bf[ni]);
        }
        __syncthreads();   // As[t&1] safe to rewrite at t+2 only after all reads
    }

    // epilogue: tanh -> fp16
    const int row0 = rowBase + warpM + (lane >> 2);
    const int col0 = colBase + warpN + (lane & 3) * 2;
#pragma unroll
    for (int mi = 0; mi < 2; mi++)
#pragma unroll
        for (int ni = 0; ni < 2; ni++)
#pragma unroll
            for (int half = 0; half < 2; half++) {
                int row = row0 + mi * 16 + half * 8;
                int col = col0 + ni * 8;
                float v0 = tanhf(acc[mi][ni][half * 2 + 0]);
                float v1 = tanhf(acc[mi][ni][half * 2 + 1]);
                *(uint32_t*)(h16 + (size_t)row * DM4 + col) = h2u(v0, v1);
            }
}

// ---------------- fused mix kernel: stage all 4 f, single epilogue ----------------
#define HST2 136
#define BST2 72
#define MIX_SMEM ((64*HST2 + 128*BST2 + 4*64*BST2) * 2)

__global__ void __launch_bounds__(256, 3)
k_mix(const __half* __restrict__ h16, const __half* __restrict__ w2h,
      const float* __restrict__ xf,
      const float* __restrict__ tmw, const float* __restrict__ tmk,
      const float* __restrict__ tmv, const float* __restrict__ tmr,
      __half* __restrict__ oxw, __half* __restrict__ oxk,
      __half* __restrict__ oxv, __half* __restrict__ oxr)
{
    extern __shared__ char smem[];
    uint16_t* hs  = (uint16_t*)smem;                                  // [64][136]
    uint16_t* wsm = (uint16_t*)(smem + 64 * HST2 * 2);                // [128][72]
    uint16_t* st  = (uint16_t*)(smem + (64 * HST2 + 128 * BST2) * 2); // [4][64][72]

    const int tid  = threadIdx.x;
    const int wid  = tid >> 5;
    const int lane = tid & 31;
    const int warpM = (wid >> 2) * 32;
    const int warpN = (wid & 3) * 16;
    const int rowBase = blockIdx.x * 64;
    const int colBase = blockIdx.y * 64;

    const uint32_t hsB = smem_u32(hs);
    const uint32_t wB  = smem_u32(wsm);

#pragma unroll
    for (int i = 0; i < 4; i++) {
        int idx = i * 256 + tid;
        int r = idx >> 4, ch = idx & 15;
        cp16(hsB + (uint32_t)(r * HST2 + ch * 8) * 2,
             h16 + (size_t)(rowBase + r) * DM4 + ch * 8);
    }
#pragma unroll
    for (int i = 0; i < 4; i++) {
        int idx = i * 256 + tid;
        int r = idx >> 3, ch = idx & 7;
        cp16(wB + (uint32_t)(r * BST2 + ch * 8) * 2,
             w2h + (size_t)r * Cc + colBase + ch * 8);
    }
    CP_COMMIT();
    CP_WAIT0();
    __syncthreads();

    const int lrow  = lane & 15;
    const int lhalf = (lane >> 4) * 8;
    const uint32_t aLane = (uint32_t)((warpM + lrow) * HST2 + lhalf) * 2;
    const uint32_t bLane = (uint32_t)(lrow * BST2 + warpN + lhalf) * 2;

#pragma unroll
    for (int f = 0; f < 4; f++) {
        float acc[2][2][4];
#pragma unroll
        for (int i = 0; i < 2; i++)
#pragma unroll
            for (int j = 0; j < 2; j++)
#pragma unroll
                for (int e = 0; e < 4; e++) acc[i][j][e] = 0.f;

#pragma unroll
        for (int k16 = 0; k16 < 2; ++k16) {
            uint32_t af[2][4];
            uint32_t bf[2][2];
#pragma unroll
            for (int mi = 0; mi < 2; mi++)
                ldsm4(af[mi], hsB + aLane + (uint32_t)(mi * 16 * HST2 + f * 32 + k16 * 16) * 2);
            ldsm4t(&bf[0][0], wB + bLane + (uint32_t)((f * 32 + k16 * 16) * BST2) * 2);
#pragma unroll
            for (int mi = 0; mi < 2; mi++)
#pragma unroll
                for (int ni = 0; ni < 2; ni++)
                    mma16816(acc[mi][ni], af[mi], bf[ni]);
        }

#pragma unroll
        for (int mi = 0; mi < 2; mi++)
#pragma unroll
            for (int ni = 0; ni < 2; ni++)
#pragma unroll
                for (int half = 0; half < 2; half++) {
                    int srow = warpM + mi * 16 + half * 8 + (lane >> 2);
                    int scol = warpN + ni * 8 + (lane & 3) * 2;
                    *(uint32_t*)&st[(f * 64 + srow) * BST2 + scol] =
                        h2u(acc[mi][ni][half * 2], acc[mi][ni][half * 2 + 1]);
                }
    }
    __syncthreads();

    // single epilogue: read x (and x_prev) once, write all 4 outputs
#pragma unroll
    for (int it = 0; it < 2; ++it) {
        int idx = it * 256 + tid;
        int row = idx >> 3, seg = idx & 7;
        int gcol = colBase + seg * 8;
        int grow = rowBase + row;
        size_t goff = (size_t)grow * Cc + gcol;
        float4 xa = *(const float4*)(xf + goff);
        float4 xb = *(const float4*)(xf + goff + 4);
        float4 pa, pb;
        if ((grow & (Tc - 1)) == 0) {
            pa = make_float4(0.f, 0.f, 0.f, 0.f);
            pb = pa;
        } else {
            pa = *(const float4*)(xf + goff - Cc);
            pb = *(const float4*)(xf + goff - Cc + 4);
        }
        float4 xxa, xxb;
        xxa.x = pa.x - xa.x; xxa.y = pa.y - xa.y; xxa.z = pa.z - xa.z; xxa.w = pa.w - xa.w;
        xxb.x = pb.x - xb.x; xxb.y = pb.y - xb.y; xxb.z = pb.z - xb.z; xxb.w = pb.w - xb.w;
#pragma unroll
        for (int f = 0; f < 4; f++) {
            const float* tmf = (f == 0) ? tmw : (f == 1) ? tmk : (f == 2) ? tmv : tmr;
            __half* of = (f == 0) ? oxw : (f == 1) ? oxk : (f == 2) ? oxv : oxr;
            uint4 mv = *(uint4*)&st[(f * 64 + row) * BST2 + seg * 8];
            float4 ta = *(const float4*)(tmf + gcol);
            float4 tb = *(const float4*)(tmf + gcol + 4);
            __half2 m0 = *(__half2*)&mv.x;
            __half2 m1 = *(__half2*)&mv.y;
            __half2 m2 = *(__half2*)&mv.z;
            __half2 m3 = *(__half2*)&mv.w;
            float v0 = fmaf(xxa.x, ta.x + __low2float(m0),  xa.x);
            float v1 = fmaf(xxa.y, ta.y + __high2float(m0), xa.y);
            float v2 = fmaf(xxa.z, ta.z + __low2float(m1),  xa.z);
            float v3 = fmaf(xxa.w, ta.w + __high2float(m1), xa.w);
            float v4 = fmaf(xxb.x, tb.x + __low2float(m2),  xb.x);
            float v5 = fmaf(xxb.y, tb.y + __high2float(m2), xb.y);
            float v6 = fmaf(xxb.z, tb.z + __low2float(m3),  xb.z);
            float v7 = fmaf(xxb.w, tb.w + __high2float(m3), xb.w);
            uint4 o;
            o.x = h2u(v0, v1); o.y = h2u(v2, v3);
            o.z = h2u(v4, v5); o.w = h2u(v6, v7);
            *(uint4*)(of + goff) = o;
        }
    }
}

// ---------------- WKV6 chunked scan (k/v/r fp16, w fp32) ----------------
#define WKV_CT 64

__global__ void __launch_bounds__(64) k_wkv1(const __half* __restrict__ k,
                                             const __half* __restrict__ v,
                                             const float* __restrict__ w,
                                             float* __restrict__ Sseg,
                                             float* __restrict__ Wseg)
{
    const int p  = blockIdx.x;
    const int bh = blockIdx.y;
    const int b = bh >> 6, h = bh & 63;
    const int tid  = threadIdx.x;
    const int wq   = tid >> 5;
    const int lane = tid & 31;
    const int j  = wq * 8 + (lane & 7);
    const int ig = lane >> 3;
    const int base = (b * Tc + p * TSEG) * (Hc * HSc) + h * HSc;

    __shared__ __align__(16) __half ks16[2][WKV_CT][16];
    __shared__ __align__(16) __half vs16[2][WKV_CT][16];
    __shared__ __align__(16) float  ws  [2][WKV_CT][16];

    float S0 = 0.f, S1 = 0.f, S2 = 0.f, S3 = 0.f;
    float wp0 = 1.f, wp1 = 1.f, wp2 = 1.f, wp3 = 1.f;

    auto issue_chunk = [&](int t0, int buf) {
#pragma unroll
        for (int i = 0; i < 2; i++) {
            int idx = i * 64 + tid;
            int tt = idx >> 1;
            int i8 = (idx & 1) * 8;
            int off = base + (t0 + tt) * (Hc * HSc) + i8;
            cp16(smem_u32(&ks16[buf][tt][i8]), k + off);
            cp16(smem_u32(&vs16[buf][tt][i8]), v + off);
        }
#pragma unroll
        for (int i = 0; i < 4; i++) {
            int idx = i * 64 + tid;
            int tt = idx >> 2;
            int i4 = (idx & 3) * 4;
            int off = base + (t0 + tt) * (Hc * HSc) + i4;
            cp16(smem_u32(&ws[buf][tt][i4]), w + off);
        }
        CP_COMMIT();
    };

    issue_chunk(0, 0);
    const int nChunks = TSEG / WKV_CT;
    for (int c = 0; c < nChunks; ++c) {
        const int buf = c & 1;
        if (c + 1 < nChunks) {
            issue_chunk((c + 1) * WKV_CT, buf ^ 1);
            CP_WAIT1();
        } else {
            CP_WAIT0();
        }
        __syncthreads();
        for (int tt = 0; tt < WKV_CT; ++tt) {
            uint2 kraw = *(const uint2*)&ks16[buf][tt][ig * 4];
            float2 k01 = __half22float2(*(const __half2*)&kraw.x);
            float2 k23 = __half22float2(*(const __half2*)&kraw.y);
            float4 ww = *(const float4*)&ws[buf][tt][ig * 4];
            float vj = __half2float(vs16[buf][tt][j]);
            S0 = fmaf(ww.x, S0, k01.x * vj);
            S1 = fmaf(ww.y, S1, k01.y * vj);
            S2 = fmaf(ww.z, S2, k23.x * vj);
            S3 = fmaf(ww.w, S3, k23.y * vj);
            wp0 *= ww.x; wp1 *= ww.y; wp2 *= ww.z; wp3 *= ww.w;
        }
        __syncthreads();
    }

    const size_t so = ((size_t)(bh * P_SEG + p) << 8) + (ig * 4) * 16 + j;
    Sseg[so]      = S0;
    Sseg[so + 16] = S1;
    Sseg[so + 32] = S2;
    Sseg[so + 48] = S3;
    if (wq == 0 && (lane & 7) == 0) {
        float* wo = Wseg + (size_t)(bh * P_SEG + p) * 16 + ig * 4;
        wo[0] = wp0; wo[1] = wp1; wo[2] = wp2; wo[3] = wp3;
    }
}

// pass 2: inline prefix scan over segments, then replay with y output
__global__ void __launch_bounds__(64) k_wkv2(const float* __restrict__ u_faaaa,
                                             const __half* __restrict__ r,
                                             const __half* __restrict__ k,
                                             const __half* __restrict__ v,
                                             const float* __restrict__ w,
                                             const float* __restrict__ Sseg,
                                             const float* __restrict__ Wseg,
                                             float* __restrict__ y)
{
    const int p  = blockIdx.x;
    const int bh = blockIdx.y;
    const int b = bh >> 6, h = bh & 63;
    const int tid  = threadIdx.x;
    const int wq   = tid >> 5;
    const int lane = tid & 31;
    const int j  = wq * 8 + (lane & 7);
    const int ig = lane >> 3;
    const int base = (b * Tc + p * TSEG) * (Hc * HSc) + h * HSc;

    __shared__ __align__(16) __half rs16[2][WKV_CT][16];
    __shared__ __align__(16) __half ks16[2][WKV_CT][16];
    __shared__ __align__(16) __half vs16[2][WKV_CT][16];
    __shared__ __align__(16) float  ws  [2][WKV_CT][16];

    auto issue_chunk = [&](int t0, int buf) {
#pragma unroll
        for (int i = 0; i < 2; i++) {
            int idx = i * 64 + tid;
            int tt = idx >> 1;
            int i8 = (idx & 1) * 8;
            int off = base + (t0 + tt) * (Hc * HSc) + i8;
            cp16(smem_u32(&rs16[buf][tt][i8]), r + off);
            cp16(smem_u32(&ks16[buf][tt][i8]), k + off);
            cp16(smem_u32(&vs16[buf][tt][i8]), v + off);
        }
#pragma unroll
        for (int i = 0; i < 4; i++) {
            int idx = i * 64 + tid;
            int tt = idx >> 2;
            int i4 = (idx & 3) * 4;
            int off = base + (t0 + tt) * (Hc * HSc) + i4;
            cp16(smem_u32(&ws[buf][tt][i4]), w + off);
        }
        CP_COMMIT();
    };

    issue_chunk(0, 0);   // overlap with the prefix scan below

    // inline prefix scan over segments m < p (same order as old k_wscan)
    float S0 = 0.f, S1 = 0.f, S2 = 0.f, S3 = 0.f;
    {
        const size_t cell = (size_t)(ig * 4) * 16 + j;
        for (int m = 0; m < p; ++m) {
            size_t o = ((size_t)(bh * P_SEG + m) << 8) + cell;
            const float* wpm = Wseg + (size_t)(bh * P_SEG + m) * 16 + ig * 4;
            float w0 = wpm[0], w1 = wpm[1], w2 = wpm[2], w3 = wpm[3];
            S0 = fmaf(w0, S0, Sseg[o]);
            S1 = fmaf(w1, S1, Sseg[o + 16]);
            S2 = fmaf(w2, S2, Sseg[o + 32]);
            S3 = fmaf(w3, S3, Sseg[o + 48]);
        }
    }
    const float4 u4 = *(const float4*)(u_faaaa + h * HSc + ig * 4);

    const int nChunks = TSEG / WKV_CT;
    for (int c = 0; c < nChunks; ++c) {
        const int buf = c & 1;
        if (c + 1 < nChunks) {
            issue_chunk((c + 1) * WKV_CT, buf ^ 1);
            CP_WAIT1();
        } else {
            CP_WAIT0();
        }
        __syncthreads();

        const int ybase = base + c * WKV_CT * (Hc * HSc) + j;
        for (int tt = 0; tt < WKV_CT; ++tt) {
            uint2 rraw = *(const uint2*)&rs16[buf][tt][ig * 4];
            uint2 kraw = *(const uint2*)&ks16[buf][tt][ig * 4];
            float2 r01 = __half22float2(*(const __half2*)&rraw.x);
            float2 r23 = __half22float2(*(const __half2*)&rraw.y);
            float2 k01 = __half22float2(*(const __half2*)&kraw.x);
            float2 k23 = __half22float2(*(const __half2*)&kraw.y);
            float4 ww = *(const float4*)&ws[buf][tt][ig * 4];
            float vj = __half2float(vs16[buf][tt][j]);
            float kv, acc;
            kv = k01.x * vj; acc = r01.x * fmaf(u4.x, kv, S0);           S0 = fmaf(ww.x, S0, kv);
            kv = k01.y * vj; acc = fmaf(r01.y, fmaf(u4.y, kv, S1), acc); S1 = fmaf(ww.y, S1, kv);
            kv = k23.x * vj; acc = fmaf(r23.x, fmaf(u4.z, kv, S2), acc); S2 = fmaf(ww.z, S2, kv);
            kv = k23.y * vj; acc = fmaf(r23.y, fmaf(u4.w, kv, S3), acc); S3 = fmaf(ww.w, S3, kv);
            acc += __shfl_xor_sync(0xffffffffu, acc, 8);
            acc += __shfl_xor_sync(0xffffffffu, acc, 16);
            if (ig == 0) y[ybase + tt * (Hc * HSc)] = acc;
        }
        __syncthreads();
    }
}

// ---------------- LayerNorm -> fp16 ----------------
__global__ void __launch_bounds__(256) k_ln(const float* __restrict__ y,
                                            const float* __restrict__ g,
                                            const float* __restrict__ bb,
                                            uint2* __restrict__ out16)
{
    const int n   = blockIdx.x;
    const int tid = threadIdx.x;
    const float4* yr = (const float4*)(y + (size_t)n * Cc);
    float4 vv = yr[tid];
    float s = vv.x + vv.y + vv.z + vv.w;
    float q = vv.x * vv.x + vv.y * vv.y + vv.z * vv.z + vv.w * vv.w;
#pragma unroll
    for (int o = 16; o > 0; o >>= 1) {
        s += __shfl_xor_sync(0xffffffffu, s, o);
        q += __shfl_xor_sync(0xffffffffu, q, o);
    }
    __shared__ float ssh[8], qsh[8];
    if ((tid & 31) == 0) { ssh[tid >> 5] = s; qsh[tid >> 5] = q; }
    __syncthreads();
    float st = 0.f, qt = 0.f;
#pragma unroll
    for (int wix = 0; wix < 8; wix++) { st += ssh[wix]; qt += qsh[wix]; }
    float mean = st * (1.0f / Cc);
    float var  = qt * (1.0f / Cc) - mean * mean;
    float rstd = rsqrtf(var + 1e-5f);
    float4 gg = ((const float4*)g)[tid];
    float4 b4 = ((const float4*)bb)[tid];
    float4 o;
    o.x = (vv.x - mean) * rstd * gg.x + b4.x;
    o.y = (vv.y - mean) * rstd * gg.y + b4.y;
    o.z = (vv.z - mean) * rstd * gg.z + b4.z;
    o.w = (vv.w - mean) * rstd * gg.w + b4.w;
    out16[(size_t)n * (Cc / 4) + tid] = f4toh(o);
}

// ---------------- launcher ----------------
// BK=64, 3 stages
#define SM128_64 (3*(128*72*2 + 64*136*2))
#define SM64_64  (3*(64*72*2 + 64*72*2))
#define SM64_128 (3*(64*72*2 + 64*136*2))

extern "C" void kernel_launch(void* const* d_in, const int* in_sizes, int n_in,
                              void* d_out, int out_size)
{
    (void)in_sizes; (void)n_in; (void)out_size;
    const float* x     = (const float*)d_in[0];
    const float* tmx   = (const float*)d_in[1];
    const float* tmw   = (const float*)d_in[2];
    const float* tmk   = (const float*)d_in[3];
    const float* tmv   = (const float*)d_in[4];
    const float* tmr   = (const float*)d_in[5];
    const float* w1    = (const float*)d_in[6];
    const float* w2    = (const float*)d_in[7];
    const float* tdec  = (const float*)d_in[8];
    const float* dw1   = (const float*)d_in[9];
    const float* dw2   = (const float*)d_in[10];
    const float* faaaa = (const float*)d_in[11];
    const float* Wr    = (const float*)d_in[12];
    const float* Wk    = (const float*)d_in[13];
    const float* Wv    = (const float*)d_in[14];
    const float* Wo    = (const float*)d_in[15];
    const float* lng   = (const float*)d_in[16];
    const float* lnb   = (const float*)d_in[17];
    float* out = (float*)d_out;

    static float *p_y = nullptr, *p_we, *p_ss, *p_wp;
    static __half *p16_yn, *p16_xw, *p16_xk, *p16_xv, *p16_xr,
                  *p16_r, *p16_k, *p16_v, *p16_h, *p16_t1,
                  *p16_wr, *p16_wk, *p16_wv, *p16_wo, *p16_w1, *p16_dw1, *p16_dw2, *p16_w2;
    if (!p_y) {
        cudaGetSymbolAddress((void**)&p_y,     g_y);
        cudaGetSymbolAddress((void**)&p_we,    g_we);
        cudaGetSymbolAddress((void**)&p_ss,    g_sseg);
        cudaGetSymbolAddress((void**)&p_wp,    g_wp);
        cudaGetSymbolAddress((void**)&p16_yn,  g16_yn);
        cudaGetSymbolAddress((void**)&p16_xw,  g16_xw);
        cudaGetSymbolAddress((void**)&p16_xk,  g16_xk);
        cudaGetSymbolAddress((void**)&p16_xv,  g16_xv);
        cudaGetSymbolAddress((void**)&p16_xr,  g16_xr);
        cudaGetSymbolAddress((void**)&p16_r,   g16_r);
        cudaGetSymbolAddress((void**)&p16_k,   g16_k);
        cudaGetSymbolAddress((void**)&p16_v,   g16_v);
        cudaGetSymbolAddress((void**)&p16_h,   g16_h);
        cudaGetSymbolAddress((void**)&p16_t1,  g16_t1);
        cudaGetSymbolAddress((void**)&p16_wr,  g16_wr);
        cudaGetSymbolAddress((void**)&p16_wk,  g16_wk);
        cudaGetSymbolAddress((void**)&p16_wv,  g16_wv);
        cudaGetSymbolAddress((void**)&p16_wo,  g16_wo);
        cudaGetSymbolAddress((void**)&p16_w1,  g16_w1);
        cudaGetSymbolAddress((void**)&p16_dw1, g16_dw1);
        cudaGetSymbolAddress((void**)&p16_dw2, g16_dw2);
        cudaGetSymbolAddress((void**)&p16_w2,  g16_w2);
        cudaFuncSetAttribute(gemmh<64,128,EPI_NONE,0>,  cudaFuncAttributeMaxDynamicSharedMemorySize, SM64_128);
        cudaFuncSetAttribute(gemmh<64,64,EPI_TANH,1>,   cudaFuncAttributeMaxDynamicSharedMemorySize, SM64_64);
        cudaFuncSetAttribute(gemmh_batch, cudaFuncAttributeMaxDynamicSharedMemorySize, SM128_64);
        cudaFuncSetAttribute(k_mix, cudaFuncAttributeMaxDynamicSharedMemorySize, MIX_SMEM);
    }

    // 0) weight converts — single launch, 8 segments (counts in float4)
    {
        CvtArgs a;
        const float* srcs[8] = { Wr, Wk, Wv, Wo, w1, dw1, dw2, w2 };
        __half* dsts[8] = { p16_wr, p16_wk, p16_wv, p16_wo, p16_w1, p16_dw1, p16_dw2, p16_w2 };
        int cnts[8] = { Cc*Cc/4, Cc*Cc/4, Cc*Cc/4, Cc*Cc/4, Cc*DM4/4, Cc*DDEC/4, DDEC*Cc/4, 4*32*Cc/4 };
        int cum = 0;
        for (int i = 0; i < 8; i++) {
            a.s[i] = (const float4*)srcs[i];
            a.d[i] = (uint2*)dsts[i];
            a.off[i] = cum;
            cum += cnts[i];
        }
        a.off[8] = cum;
        k_cvt<<<(cum + 255) / 256, 256>>>(a);
    }

    // 1) fused shift + h-GEMM: h = tanh(xxx @ w1), xxx built on the fly
    k_hshift<<<dim3(NTOK/64, DM4/64), 256>>>(x, tmx, p16_w1, p16_h);

    // 2) fused mix: xw/xk/xv/xr (xx computed inline from x)
    k_mix<<<dim3(NTOK/64, Cc/64), 256, MIX_SMEM>>>(
        p16_h, p16_w2, x, tmw, tmk, tmv, tmr,
        p16_xw, p16_xk, p16_xv, p16_xr);

    // 3) t1 = tanh(xw @ dw1)  K=1024 -> nT=16
    gemmh<64,64,EPI_TANH,1><<<dim3(NTOK/64, 1), 256, SM64_64>>>(
        p16_xw, p16_dw1, p16_t1, Cc/64, Cc, DDEC, DDEC, nullptr);

    // 4) batched: r/k/v projections (fp16 out) + wexp
    {
        BatchArgs ba;
        ba.A[0] = p16_xr; ba.B[0] = p16_wr; ba.C[0] = p16_r; ba.nT[0] = Cc/64; ba.lda[0] = Cc;
        ba.A[1] = p16_xk; ba.B[1] = p16_wk; ba.C[1] = p16_k; ba.nT[1] = Cc/64; ba.lda[1] = Cc;
        ba.A[2] = p16_xv; ba.B[2] = p16_wv; ba.C[2] = p16_v; ba.nT[2] = Cc/64; ba.lda[2] = Cc;
        ba.A[3] = p16_t1; ba.B[3] = p16_dw2; ba.C[3] = p_we; ba.nT[3] = DDEC/64; ba.lda[3] = DDEC;
        ba.bias = tdec;
        gemmh_batch<<<dim3(NTOK/128, Cc/128, 4), 256, SM128_64>>>(ba);
    }

    // 5) WKV6 chunked scan (scan fused into pass 2)
    k_wkv1<<<dim3(P_SEG, Bc * Hc), 64>>>(p16_k, p16_v, p_we, p_ss, p_wp);
    k_wkv2<<<dim3(P_SEG, Bc * Hc), 64>>>(faaaa, p16_r, p16_k, p16_v, p_we, p_ss, p_wp, p_y);

    // 6) LayerNorm -> fp16
    k_ln<<<NTOK, 256>>>(p_y, lng, lnb, (uint2*)p16_yn);

    // 7) out = yn @ Wo  — 64x128 tiles for better wave quantization
    gemmh<64,128,EPI_NONE,0><<<dim3(NTOK/64, Cc/128), 256, SM64_128>>>(
        p16_yn, p16_wo, out, Cc/64, Cc, Cc, Cc, nullptr);
}

// round 16
// speedup vs baseline: 1.0160x; 1.0160x over previous
#include <cuda_runtime.h>
#include <cuda_fp16.h>
#include <math.h>
#include <cstdint>

// ---------------- problem constants ----------------
#define Bc    4
#define Tc    2048
#define Cc    1024
#define Hc    64
#define HSc   16
#define NTOK  (Bc*Tc)            // 8192
#define C4    (Cc/4)             // 256
#define NC    (NTOK*Cc)
#define DM4   128
#define DDEC  64
#define P_SEG 16
#define TSEG  (Tc/P_SEG)         // 128
#define NSEG  (Bc*Hc*P_SEG)      // 4096

// ---------------- scratch ----------------
// fp32
__device__ __align__(16) float g_y  [NC];
__device__ __align__(16) float g_we [NC];
__device__ __align__(16) float g_sseg[NSEG*256];
__device__ __align__(16) float g_wp  [NSEG*16];
// fp16 activations
__device__ __align__(16) __half g16_yn [NC];
__device__ __align__(16) __half g16_xw [NC];
__device__ __align__(16) __half g16_xk [NC];
__device__ __align__(16) __half g16_xv [NC];
__device__ __align__(16) __half g16_xr [NC];
__device__ __align__(16) __half g16_r  [NC];
__device__ __align__(16) __half g16_k  [NC];
__device__ __align__(16) __half g16_v  [NC];
__device__ __align__(16) __half g16_h  [NTOK*DM4];
__device__ __align__(16) __half g16_t1 [NTOK*DDEC];
// fp16 weights
__device__ __align__(16) __half g16_wr [Cc*Cc];
__device__ __align__(16) __half g16_wk [Cc*Cc];
__device__ __align__(16) __half g16_wv [Cc*Cc];
__device__ __align__(16) __half g16_wo [Cc*Cc];
__device__ __align__(16) __half g16_w1 [Cc*DM4];
__device__ __align__(16) __half g16_dw1[Cc*DDEC];
__device__ __align__(16) __half g16_dw2[DDEC*Cc];
__device__ __align__(16) __half g16_w2 [4*32*Cc];

// ---------------- helpers ----------------
__device__ __forceinline__ uint32_t smem_u32(const void* p) {
    uint32_t a;
    asm("{ .reg .u64 t; cvta.to.shared.u64 t, %1; cvt.u32.u64 %0, t; }" : "=r"(a) : "l"(p));
    return a;
}
__device__ __forceinline__ void ldsm4(uint32_t* r, uint32_t addr) {
    asm volatile("ldmatrix.sync.aligned.m8n8.x4.shared.b16 {%0,%1,%2,%3}, [%4];"
        : "=r"(r[0]), "=r"(r[1]), "=r"(r[2]), "=r"(r[3]) : "r"(addr));
}
__device__ __forceinline__ void ldsm4t(uint32_t* r, uint32_t addr) {
    asm volatile("ldmatrix.sync.aligned.m8n8.x4.trans.shared.b16 {%0,%1,%2,%3}, [%4];"
        : "=r"(r[0]), "=r"(r[1]), "=r"(r[2]), "=r"(r[3]) : "r"(addr));
}
__device__ __forceinline__ void mma16816(float* d, const uint32_t* a, const uint32_t* b) {
    asm volatile(
        "mma.sync.aligned.m16n8k16.row.col.f32.f16.f16.f32 "
        "{%0,%1,%2,%3}, {%4,%5,%6,%7}, {%8,%9}, {%0,%1,%2,%3};"
        : "+f"(d[0]), "+f"(d[1]), "+f"(d[2]), "+f"(d[3])
        : "r"(a[0]), "r"(a[1]), "r"(a[2]), "r"(a[3]), "r"(b[0]), "r"(b[1]));
}
__device__ __forceinline__ void cp16(uint32_t sdst, const void* gsrc) {
    asm volatile("cp.async.cg.shared.global [%0], [%1], 16;" :: "r"(sdst), "l"(gsrc));
}
#define CP_COMMIT() asm volatile("cp.async.commit_group;")
#define CP_WAIT1()  asm volatile("cp.async.wait_group 1;")
#define CP_WAIT0()  asm volatile("cp.async.wait_group 0;")

__device__ __forceinline__ uint32_t h2u(float a, float b) {
    __half2 h = __floats2half2_rn(a, b);
    return *reinterpret_cast<uint32_t*>(&h);
}
__device__ __forceinline__ uint2 f4toh(float4 v) {
    return make_uint2(h2u(v.x, v.y), h2u(v.z, v.w));
}

// ---------------- one-shot weight convert (8 segments) ----------------
struct CvtArgs {
    const float4* s[8];
    uint2* d[8];
    int off[9];
};
__global__ void __launch_bounds__(256) k_cvt(CvtArgs a) {
    int i = blockIdx.x * 256 + threadIdx.x;
    if (i >= a.off[8]) return;
#pragma unroll
    for (int sg = 0; sg < 8; sg++) {
        if (i < a.off[sg + 1]) {
            int j = i - a.off[sg];
            a.d[sg][j] = f4toh(a.s[sg][j]);
            return;
        }
    }
}

// ---------------- GEMM: fp16, cp.async 3-stage BK=64, mma.sync ----------------
enum { EPI_NONE = 0, EPI_TANH = 1, EPI_WEXP = 2 };

template<int BM, int BN, int EPI, int OUTH>
struct GemmBody {
    static __device__ __forceinline__ void run(
        const __half* __restrict__ A, const __half* __restrict__ B,
        void* __restrict__ C, int nT, int lda, int ldb, int ldc,
        const float* __restrict__ bias, char* smem,
        int rowBase, int colBase)
    {
        constexpr int BK   = 64;
        constexpr int S    = 3;
        constexpr int ASTR = BK + 8;      // 72
        constexpr int BSTR = BN + 8;
        constexpr int ABYT = BM * ASTR * 2;
        constexpr int BBYT = BK * BSTR * 2;
        constexpr int MFR  = (BM + 31) / 32;
        constexpr int NFR  = BN / 32;
        constexpr int A_CH = BM * (BK / 8) / 256;
        constexpr int B_CH = BK * (BN / 8) / 256;
        constexpr int ASH  = (BK == 64) ? 3 : 2;
        constexpr int BSH  = (BN == 128) ? 4 : 3;
        constexpr int KH   = BK / 16;
        constexpr int MROWS = BM / 2;     // rows per warp-group half

        char* As = smem;
        char* Bs = smem + S * ABYT;

        const int tid  = threadIdx.x;
        const int wid  = tid >> 5;
        const int lane = tid & 31;
        const int warpM = (wid >> 2) * MROWS;
        const int warpN = (wid & 3) * (BN / 4);

        const uint32_t aBase = smem_u32(As);
        const uint32_t bBase = smem_u32(Bs);
        const int lrow  = lane & 15;
        const int lhalf = (lane >> 4) * 8;
        const uint32_t aLane = (uint32_t)((warpM + lrow) * ASTR + lhalf) * 2;
        const uint32_t bLane = (uint32_t)(lrow * BSTR + warpN + lhalf) * 2;

        constexpr int MI = MROWS / 16;    // m-frags per warp
        float acc[MI][NFR][4];
#pragma unroll
        for (int i = 0; i < MI; i++)
#pragma unroll
            for (int j = 0; j < NFR; j++)
#pragma unroll
                for (int e = 0; e < 4; e++) acc[i][j][e] = 0.f;

        auto issue = [&](int t) {
            const int kt = t * BK;
            const int sb = t % S;
            uint32_t ad = aBase + sb * ABYT;
            uint32_t bd = bBase + sb * BBYT;
#pragma unroll
            for (int i = 0; i < A_CH; i++) {
                int idx = i * 256 + tid;
                int r = idx >> ASH, ch = idx & ((1 << ASH) - 1);
                cp16(ad + (uint32_t)(r * ASTR + ch * 8) * 2,
                     A + (size_t)(rowBase + r) * lda + kt + ch * 8);
            }
#pragma unroll
            for (int i = 0; i < B_CH; i++) {
                int idx = i * 256 + tid;
                int r = idx >> BSH, ch = idx & ((1 << BSH) - 1);
                cp16(bd + (uint32_t)(r * BSTR + ch * 8) * 2,
                     B + (size_t)(kt + r) * ldb + colBase + ch * 8);
            }
        };

#pragma unroll
        for (int s = 0; s < S - 1; ++s) {
            if (s < nT) issue(s);
            CP_COMMIT();
        }

        for (int t = 0; t < nT; ++t) {
            CP_WAIT1();
            __syncthreads();
            if (t + S - 1 < nT) issue(t + S - 1);
            CP_COMMIT();

            const int sb = t % S;
            const uint32_t ad = aBase + sb * ABYT;
            const uint32_t bd = bBase + sb * BBYT;
#pragma unroll
            for (int k16 = 0; k16 < KH; ++k16) {
                uint32_t af[MI][4];
                uint32_t bf[NFR][2];
#pragma unroll
                for (int mi = 0; mi < MI; mi++)
                    ldsm4(af[mi], ad + aLane + (uint32_t)(mi * 16 * ASTR + k16 * 16) * 2);
#pragma unroll
                for (int p = 0; p < NFR / 2; p++)
                    ldsm4t(&bf[p * 2][0], bd + bLane + (uint32_t)(k16 * 16 * BSTR + p * 16) * 2);
#pragma unroll
                for (int mi = 0; mi < MI; mi++)
#pragma unroll
                    for (int ni = 0; ni < NFR; ni++)
                        mma16816(acc[mi][ni], af[mi], bf[ni]);
            }
        }

        // ---- epilogue ----
        const int row0 = rowBase + warpM + (lane >> 2);
        const int col0 = colBase + warpN + (lane & 3) * 2;
#pragma unroll
        for (int mi = 0; mi < MI; mi++) {
#pragma unroll
            for (int ni = 0; ni < NFR; ni++) {
#pragma unroll
                for (int half = 0; half < 2; half++) {
                    int row = row0 + mi * 16 + half * 8;
                    int col = col0 + ni * 8;
                    float v0 = acc[mi][ni][half * 2 + 0];
                    float v1 = acc[mi][ni][half * 2 + 1];
                    if (EPI == EPI_TANH) {
                        v0 = tanhf(v0); v1 = tanhf(v1);
                    } else if (EPI == EPI_WEXP) {
                        v0 = expf(-expf(bias[col] + v0));
                        v1 = expf(-expf(bias[col + 1] + v1));
                    }
                    if (OUTH) {
                        *(uint32_t*)((__half*)C + (size_t)row * ldc + col) = h2u(v0, v1);
                    } else {
                        float* co = (float*)C + (size_t)row * ldc + col;
                        co[0] = v0; co[1] = v1;
                    }
                }
            }
        }
    }
};

template<int BM, int BN, int EPI, int OUTH>
__global__ void __launch_bounds__(256, 2)
gemmh(const __half* __restrict__ A, const __half* __restrict__ B,
      void* __restrict__ C, int nT, int lda, int ldb, int ldc,
      const float* __restrict__ bias)
{
    extern __shared__ char smem[];
    GemmBody<BM, BN, EPI, OUTH>::run(A, B, C, nT, lda, ldb, ldc, bias, smem,
                                     blockIdx.x * BM, blockIdx.y * BN);
}

// batched: z=0..2 -> r/k/v projections (fp16 out), z=3 -> wexp (fp32 out)
struct BatchArgs {
    const __half* A[4]; const __half* B[4]; void* C[4];
    int nT[4]; int lda[4];
    const float* bias;
};
__global__ void __launch_bounds__(256, 2)
gemmh_batch(BatchArgs args)
{
    extern __shared__ char smem[];
    const int z = blockIdx.z;
    if (z < 3) {
        GemmBody<128, 128, EPI_NONE, 1>::run(args.A[z], args.B[z], args.C[z],
                                             args.nT[z], args.lda[z], Cc, Cc, nullptr, smem,
                                             blockIdx.x * 128, blockIdx.y * 128);
    } else {
        GemmBody<128, 128, EPI_WEXP, 0>::run(args.A[3], args.B[3], args.C[3],
                                             args.nT[3], args.lda[3], Cc, Cc, args.bias, smem,
                                             blockIdx.x * 128, blockIdx.y * 128);
    }
}

// ---------------- fused shift + h-GEMM: h = tanh((x + (xprev - x)*tmx) @ w1) ----------------
#define HF_ASTR 72
#define HF_BSTR 72

__global__ void __launch_bounds__(256, 2)
k_hshift(const float* __restrict__ x, const float* __restrict__ tmx,
         const __half* __restrict__ w1h, __half* __restrict__ h16)
{
    __shared__ __half As[2][64 * HF_ASTR];
    __shared__ __half Bs[3][64 * HF_BSTR];

    const int tid  = threadIdx.x;
    const int wid  = tid >> 5;
    const int lane = tid & 31;
    const int warpM = (wid >> 2) * 32;
    const int warpN = (wid & 3) * 16;
    const int rowBase = blockIdx.x * 64;
    const int colBase = blockIdx.y * 64;
    const int nT = Cc / 64;             // 16

    const uint32_t aBase = smem_u32(As);
    const uint32_t bBase = smem_u32(Bs);

    auto issueB = [&](int t) {
        const int kt = t * 64;
        uint32_t bd = bBase + (uint32_t)((t % 3) * 64 * HF_BSTR) * 2;
#pragma unroll
        for (int i = 0; i < 2; i++) {
            int idx = i * 256 + tid;
            int r = idx >> 3, ch = idx & 7;
            cp16(bd + (uint32_t)(r * HF_BSTR + ch * 8) * 2,
                 w1h + (size_t)(kt + r) * DM4 + colBase + ch * 8);
        }
        CP_COMMIT();
    };

    float4 ax[4], ap[4];
    auto loadA = [&](int t) {
        const int kt = t * 64;
#pragma unroll
        for (int i = 0; i < 4; i++) {
            int idx = i * 256 + tid;
            int r = idx >> 4, ch = idx & 15;
            int grow = rowBase + r;
            size_t go = (size_t)grow * Cc + kt + ch * 4;
            ax[i] = *(const float4*)(x + go);
            if ((grow & (Tc - 1)) == 0)
                ap[i] = make_float4(0.f, 0.f, 0.f, 0.f);
            else
                ap[i] = *(const float4*)(x + go - Cc);
        }
    };

    issueB(0);
    issueB(1);
    loadA(0);

    float acc[2][2][4];
#pragma unroll
    for (int i = 0; i < 2; i++)
#pragma unroll
        for (int j = 0; j < 2; j++)
#pragma unroll
            for (int e = 0; e < 4; e++) acc[i][j][e] = 0.f;

    const int lrow  = lane & 15;
    const int lhalf = (lane >> 4) * 8;
    const uint32_t aLane = (uint32_t)((warpM + lrow) * HF_ASTR + lhalf) * 2;
    const uint32_t bLane = (uint32_t)(lrow * HF_BSTR + warpN + lhalf) * 2;

    for (int t = 0; t < nT; ++t) {
        {
            const int kt = t * 64;
            __half* dst = As[t & 1];
#pragma unroll
            for (int i = 0; i < 4; i++) {
                int idx = i * 256 + tid;
                int r = idx >> 4, ch = idx & 15;
                float4 tm = *(const float4*)(tmx + kt + ch * 4);
                float4 o;
                o.x = fmaf(ap[i].x - ax[i].x, tm.x, ax[i].x);
                o.y = fmaf(ap[i].y - ax[i].y, tm.y, ax[i].y);
                o.z = fmaf(ap[i].z - ax[i].z, tm.z, ax[i].z);
                o.w = fmaf(ap[i].w - ax[i].w, tm.w, ax[i].w);
                *(uint2*)&dst[r * HF_ASTR + ch * 4] = f4toh(o);
            }
        }
        CP_WAIT1();
        __syncthreads();
        if (t + 2 < nT) issueB(t + 2);
        if (t + 1 < nT) loadA(t + 1);

        const uint32_t ad = aBase + (uint32_t)((t & 1) * 64 * HF_ASTR) * 2;
        const uint32_t bd = bBase + (uint32_t)((t % 3) * 64 * HF_BSTR) * 2;
#pragma unroll
        for (int k16 = 0; k16 < 4; ++k16) {
            uint32_t af[2][4];
            uint32_t bf[2][2];
#pragma unroll
            for (int mi = 0; mi < 2; mi++)
                ldsm4(af[mi], ad + aLane + (uint32_t)(mi * 16 * HF_ASTR + k16 * 16) * 2);
            ldsm4t(&bf[0][0], bd + bLane + (uint32_t)(k16 * 16 * HF_BSTR) * 2);
#pragma unroll
            for (int mi = 0; mi < 2; mi++)
#pragma unroll
                for (int ni = 0; ni < 2; ni++)
                    mma16816(acc[mi][ni], af[mi], bf[ni]);
        }
        __syncthreads();
    }

    const int row0 = rowBase + warpM + (lane >> 2);
    const int col0 = colBase + warpN + (lane & 3) * 2;
#pragma unroll
    for (int mi = 0; mi < 2; mi++)
#pragma unroll
        for (int ni = 0; ni < 2; ni++)
#pragma unroll
            for (int half = 0; half < 2; half++) {
                int row = row0 + mi * 16 + half * 8;
                int col = col0 + ni * 8;
                float v0 = tanhf(acc[mi][ni][half * 2 + 0]);
                float v1 = tanhf(acc[mi][ni][half * 2 + 1]);
                *(uint32_t*)(h16 + (size_t)row * DM4 + col) = h2u(v0, v1);
            }
}

// ---------------- fused mix kernel: stage all 4 f, single epilogue ----------------
#define HST2 136
#define BST2 72
#define MIX_SMEM ((64*HST2 + 128*BST2 + 4*64*BST2) * 2)

__global__ void __launch_bounds__(256, 3)
k_mix(const __half* __restrict__ h16, const __half* __restrict__ w2h,
      const float* __restrict__ xf,
      const float* __restrict__ tmw, const float* __restrict__ tmk,
      const float* __restrict__ tmv, const float* __restrict__ tmr,
      __half* __restrict__ oxw, __half* __restrict__ oxk,
      __half* __restrict__ oxv, __half* __restrict__ oxr)
{
    extern __shared__ char smem[];
    uint16_t* hs  = (uint16_t*)smem;
    uint16_t* wsm = (uint16_t*)(smem + 64 * HST2 * 2);
    uint16_t* st  = (uint16_t*)(smem + (64 * HST2 + 128 * BST2) * 2);

    const int tid  = threadIdx.x;
    const int wid  = tid >> 5;
    const int lane = tid & 31;
    const int warpM = (wid >> 2) * 32;
    const int warpN = (wid & 3) * 16;
    const int rowBase = blockIdx.x * 64;
    const int colBase = blockIdx.y * 64;

    const uint32_t hsB = smem_u32(hs);
    const uint32_t wB  = smem_u32(wsm);

#pragma unroll
    for (int i = 0; i < 4; i++) {
        int idx = i * 256 + tid;
        int r = idx >> 4, ch = idx & 15;
        cp16(hsB + (uint32_t)(r * HST2 + ch * 8) * 2,
             h16 + (size_t)(rowBase + r) * DM4 + ch * 8);
    }
#pragma unroll
    for (int i = 0; i < 4; i++) {
        int idx = i * 256 + tid;
        int r = idx >> 3, ch = idx & 7;
        cp16(wB + (uint32_t)(r * BST2 + ch * 8) * 2,
             w2h + (size_t)r * Cc + colBase + ch * 8);
    }
    CP_COMMIT();
    CP_WAIT0();
    __syncthreads();

    const int lrow  = lane & 15;
    const int lhalf = (lane >> 4) * 8;
    const uint32_t aLane = (uint32_t)((warpM + lrow) * HST2 + lhalf) * 2;
    const uint32_t bLane = (uint32_t)(lrow * BST2 + warpN + lhalf) * 2;

#pragma unroll
    for (int f = 0; f < 4; f++) {
        float acc[2][2][4];
#pragma unroll
        for (int i = 0; i < 2; i++)
#pragma unroll
            for (int j = 0; j < 2; j++)
#pragma unroll
                for (int e = 0; e < 4; e++) acc[i][j][e] = 0.f;

#pragma unroll
        for (int k16 = 0; k16 < 2; ++k16) {
            uint32_t af[2][4];
            uint32_t bf[2][2];
#pragma unroll
            for (int mi = 0; mi < 2; mi++)
                ldsm4(af[mi], hsB + aLane + (uint32_t)(mi * 16 * HST2 + f * 32 + k16 * 16) * 2);
            ldsm4t(&bf[0][0], wB + bLane + (uint32_t)((f * 32 + k16 * 16) * BST2) * 2);
#pragma unroll
            for (int mi = 0; mi < 2; mi++)
#pragma unroll
                for (int ni = 0; ni < 2; ni++)
                    mma16816(acc[mi][ni], af[mi], bf[ni]);
        }

#pragma unroll
        for (int mi = 0; mi < 2; mi++)
#pragma unroll
            for (int ni = 0; ni < 2; ni++)
#pragma unroll
                for (int half = 0; half < 2; half++) {
                    int srow = warpM + mi * 16 + half * 8 + (lane >> 2);
                    int scol = warpN + ni * 8 + (lane & 3) * 2;
                    *(uint32_t*)&st[(f * 64 + srow) * BST2 + scol] =
                        h2u(acc[mi][ni][half * 2], acc[mi][ni][half * 2 + 1]);
                }
    }
    __syncthreads();

#pragma unroll
    for (int it = 0; it < 2; ++it) {
        int idx = it * 256 + tid;
        int row = idx >> 3, seg = idx & 7;
        int gcol = colBase + seg * 8;
        int grow = rowBase + row;
        size_t goff = (size_t)grow * Cc + gcol;
        float4 xa = *(const float4*)(xf + goff);
        float4 xb = *(const float4*)(xf + goff + 4);
        float4 pa, pb;
        if ((grow & (Tc - 1)) == 0) {
            pa = make_float4(0.f, 0.f, 0.f, 0.f);
            pb = pa;
        } else {
            pa = *(const float4*)(xf + goff - Cc);
            pb = *(const float4*)(xf + goff - Cc + 4);
        }
        float4 xxa, xxb;
        xxa.x = pa.x - xa.x; xxa.y = pa.y - xa.y; xxa.z = pa.z - xa.z; xxa.w = pa.w - xa.w;
        xxb.x = pb.x - xb.x; xxb.y = pb.y - xb.y; xxb.z = pb.z - xb.z; xxb.w = pb.w - xb.w;
#pragma unroll
        for (int f = 0; f < 4; f++) {
            const float* tmf = (f == 0) ? tmw : (f == 1) ? tmk : (f == 2) ? tmv : tmr;
            __half* of = (f == 0) ? oxw : (f == 1) ? oxk : (f == 2) ? oxv : oxr;
            uint4 mv = *(uint4*)&st[(f * 64 + row) * BST2 + seg * 8];
            float4 ta = *(const float4*)(tmf + gcol);
            float4 tb = *(const float4*)(tmf + gcol + 4);
            __half2 m0 = *(__half2*)&mv.x;
            __half2 m1 = *(__half2*)&mv.y;
            __half2 m2 = *(__half2*)&mv.z;
            __half2 m3 = *(__half2*)&mv.w;
            float v0 = fmaf(xxa.x, ta.x + __low2float(m0),  xa.x);
            float v1 = fmaf(xxa.y, ta.y + __high2float(m0), xa.y);
            float v2 = fmaf(xxa.z, ta.z + __low2float(m1),  xa.z);
            float v3 = fmaf(xxa.w, ta.w + __high2float(m1), xa.w);
            float v4 = fmaf(xxb.x, tb.x + __low2float(m2),  xb.x);
            float v5 = fmaf(xxb.y, tb.y + __high2float(m2), xb.y);
            float v6 = fmaf(xxb.z, tb.z + __low2float(m3),  xb.z);
            float v7 = fmaf(xxb.w, tb.w + __high2float(m3), xb.w);
            uint4 o;
            o.x = h2u(v0, v1); o.y = h2u(v2, v3);
            o.z = h2u(v4, v5); o.w = h2u(v6, v7);
            *(uint4*)(of + goff) = o;
        }
    }
}

// ---------------- WKV6 chunked scan (k/v/r fp16, w fp32) ----------------
#define WKV_CT 64

__global__ void __launch_bounds__(64) k_wkv1(const __half* __restrict__ k,
                                             const __half* __restrict__ v,
                                             const float* __restrict__ w,
                                             float* __restrict__ Sseg,
                                             float* __restrict__ Wseg)
{
    const int p  = blockIdx.x;
    const int bh = blockIdx.y;
    const int b = bh >> 6, h = bh & 63;
    const int tid  = threadIdx.x;
    const int wq   = tid >> 5;
    const int lane = tid & 31;
    const int j  = wq * 8 + (lane & 7);
    const int ig = lane >> 3;
    const int base = (b * Tc + p * TSEG) * (Hc * HSc) + h * HSc;

    __shared__ __align__(16) __half ks16[2][WKV_CT][16];
    __shared__ __align__(16) __half vs16[2][WKV_CT][16];
    __shared__ __align__(16) float  ws  [2][WKV_CT][16];

    float S0 = 0.f, S1 = 0.f, S2 = 0.f, S3 = 0.f;
    float wp0 = 1.f, wp1 = 1.f, wp2 = 1.f, wp3 = 1.f;

    auto issue_chunk = [&](int t0, int buf) {
#pragma unroll
        for (int i = 0; i < 2; i++) {
            int idx = i * 64 + tid;
            int tt = idx >> 1;
            int i8 = (idx & 1) * 8;
            int off = base + (t0 + tt) * (Hc * HSc) + i8;
            cp16(smem_u32(&ks16[buf][tt][i8]), k + off);
            cp16(smem_u32(&vs16[buf][tt][i8]), v + off);
        }
#pragma unroll
        for (int i = 0; i < 4; i++) {
            int idx = i * 64 + tid;
            int tt = idx >> 2;
            int i4 = (idx & 3) * 4;
            int off = base + (t0 + tt) * (Hc * HSc) + i4;
            cp16(smem_u32(&ws[buf][tt][i4]), w + off);
        }
        CP_COMMIT();
    };

    issue_chunk(0, 0);
    const int nChunks = TSEG / WKV_CT;
    for (int c = 0; c < nChunks; ++c) {
        const int buf = c & 1;
        if (c + 1 < nChunks) {
            issue_chunk((c + 1) * WKV_CT, buf ^ 1);
            CP_WAIT1();
        } else {
            CP_WAIT0();
        }
        __syncthreads();
        for (int tt = 0; tt < WKV_CT; ++tt) {
            uint2 kraw = *(const uint2*)&ks16[buf][tt][ig * 4];
            float2 k01 = __half22float2(*(const __half2*)&kraw.x);
            float2 k23 = __half22float2(*(const __half2*)&kraw.y);
            float4 ww = *(const float4*)&ws[buf][tt][ig * 4];
            float vj = __half2float(vs16[buf][tt][j]);
            S0 = fmaf(ww.x, S0, k01.x * vj);
            S1 = fmaf(ww.y, S1, k01.y * vj);
            S2 = fmaf(ww.z, S2, k23.x * vj);
            S3 = fmaf(ww.w, S3, k23.y * vj);
            wp0 *= ww.x; wp1 *= ww.y; wp2 *= ww.z; wp3 *= ww.w;
        }
        __syncthreads();
    }

    const size_t so = ((size_t)(bh * P_SEG + p) << 8) + (ig * 4) * 16 + j;
    Sseg[so]      = S0;
    Sseg[so + 16] = S1;
    Sseg[so + 32] = S2;
    Sseg[so + 48] = S3;
    if (wq == 0 && (lane & 7) == 0) {
        float* wo = Wseg + (size_t)(bh * P_SEG + p) * 16 + ig * 4;
        wo[0] = wp0; wo[1] = wp1; wo[2] = wp2; wo[3] = wp3;
    }
}

// pass 2: inline prefix scan over segments, then replay with y output
__global__ void __launch_bounds__(64) k_wkv2(const float* __restrict__ u_faaaa,
                                             const __half* __restrict__ r,
                                             const __half* __restrict__ k,
                                             const __half* __restrict__ v,
                                             const float* __restrict__ w,
                                             const float* __restrict__ Sseg,
                                             const float* __restrict__ Wseg,
                                             float* __restrict__ y)
{
    const int p  = blockIdx.x;
    const int bh = blockIdx.y;
    const int b = bh >> 6, h = bh & 63;
    const int tid  = threadIdx.x;
    const int wq   = tid >> 5;
    const int lane = tid & 31;
    const int j  = wq * 8 + (lane & 7);
    const int ig = lane >> 3;
    const int base = (b * Tc + p * TSEG) * (Hc * HSc) + h * HSc;

    __shared__ __align__(16) __half rs16[2][WKV_CT][16];
    __shared__ __align__(16) __half ks16[2][WKV_CT][16];
    __shared__ __align__(16) __half vs16[2][WKV_CT][16];
    __shared__ __align__(16) float  ws  [2][WKV_CT][16];

    auto issue_chunk = [&](int t0, int buf) {
#pragma unroll
        for (int i = 0; i < 2; i++) {
            int idx = i * 64 + tid;
            int tt = idx >> 1;
            int i8 = (idx & 1) * 8;
            int off = base + (t0 + tt) * (Hc * HSc) + i8;
            cp16(smem_u32(&rs16[buf][tt][i8]), r + off);
            cp16(smem_u32(&ks16[buf][tt][i8]), k + off);
            cp16(smem_u32(&vs16[buf][tt][i8]), v + off);
        }
#pragma unroll
        for (int i = 0; i < 4; i++) {
            int idx = i * 64 + tid;
            int tt = idx >> 2;
            int i4 = (idx & 3) * 4;
            int off = base + (t0 + tt) * (Hc * HSc) + i4;
            cp16(smem_u32(&ws[buf][tt][i4]), w + off);
        }
        CP_COMMIT();
    };

    issue_chunk(0, 0);   // overlap with the prefix scan below

    float S0 = 0.f, S1 = 0.f, S2 = 0.f, S3 = 0.f;
    {
        const size_t cell = (size_t)(ig * 4) * 16 + j;
        for (int m = 0; m < p; ++m) {
            size_t o = ((size_t)(bh * P_SEG + m) << 8) + cell;
            const float* wpm = Wseg + (size_t)(bh * P_SEG + m) * 16 + ig * 4;
            float w0 = wpm[0], w1 = wpm[1], w2 = wpm[2], w3 = wpm[3];
            S0 = fmaf(w0, S0, Sseg[o]);
            S1 = fmaf(w1, S1, Sseg[o + 16]);
            S2 = fmaf(w2, S2, Sseg[o + 32]);
            S3 = fmaf(w3, S3, Sseg[o + 48]);
        }
    }
    const float4 u4 = *(const float4*)(u_faaaa + h * HSc + ig * 4);

    const int nChunks = TSEG / WKV_CT;
    for (int c = 0; c < nChunks; ++c) {
        const int buf = c & 1;
        if (c + 1 < nChunks) {
            issue_chunk((c + 1) * WKV_CT, buf ^ 1);
            CP_WAIT1();
        } else {
            CP_WAIT0();
        }
        __syncthreads();

        const int ybase = base + c * WKV_CT * (Hc * HSc) + j;
        for (int tt = 0; tt < WKV_CT; ++tt) {
            uint2 rraw = *(const uint2*)&rs16[buf][tt][ig * 4];
            uint2 kraw = *(const uint2*)&ks16[buf][tt][ig * 4];
            float2 r01 = __half22float2(*(const __half2*)&rraw.x);
            float2 r23 = __half22float2(*(const __half2*)&rraw.y);
            float2 k01 = __half22float2(*(const __half2*)&kraw.x);
            float2 k23 = __half22float2(*(const __half2*)&kraw.y);
            float4 ww = *(const float4*)&ws[buf][tt][ig * 4];
            float vj = __half2float(vs16[buf][tt][j]);
            float kv, acc;
            kv = k01.x * vj; acc = r01.x * fmaf(u4.x, kv, S0);           S0 = fmaf(ww.x, S0, kv);
            kv = k01.y * vj; acc = fmaf(r01.y, fmaf(u4.y, kv, S1), acc); S1 = fmaf(ww.y, S1, kv);
            kv = k23.x * vj; acc = fmaf(r23.x, fmaf(u4.z, kv, S2), acc); S2 = fmaf(ww.z, S2, kv);
            kv = k23.y * vj; acc = fmaf(r23.y, fmaf(u4.w, kv, S3), acc); S3 = fmaf(ww.w, S3, kv);
            acc += __shfl_xor_sync(0xffffffffu, acc, 8);
            acc += __shfl_xor_sync(0xffffffffu, acc, 16);
            if (ig == 0) y[ybase + tt * (Hc * HSc)] = acc;
        }
        __syncthreads();
    }
}

// ---------------- LayerNorm -> fp16 ----------------
__global__ void __launch_bounds__(256) k_ln(const float* __restrict__ y,
                                            const float* __restrict__ g,
                                            const float* __restrict__ bb,
                                            uint2* __restrict__ out16)
{
    const int n   = blockIdx.x;
    const int tid = threadIdx.x;
    const float4* yr = (const float4*)(y + (size_t)n * Cc);
    float4 vv = yr[tid];
    float s = vv.x + vv.y + vv.z + vv.w;
    float q = vv.x * vv.x + vv.y * vv.y + vv.z * vv.z + vv.w * vv.w;
#pragma unroll
    for (int o = 16; o > 0; o >>= 1) {
        s += __shfl_xor_sync(0xffffffffu, s, o);
        q += __shfl_xor_sync(0xffffffffu, q, o);
    }
    __shared__ float ssh[8], qsh[8];
    if ((tid & 31) == 0) { ssh[tid >> 5] = s; qsh[tid >> 5] = q; }
    __syncthreads();
    float st = 0.f, qt = 0.f;
#pragma unroll
    for (int wix = 0; wix < 8; wix++) { st += ssh[wix]; qt += qsh[wix]; }
    float mean = st * (1.0f / Cc);
    float var  = qt * (1.0f / Cc) - mean * mean;
    float rstd = rsqrtf(var + 1e-5f);
    float4 gg = ((const float4*)g)[tid];
    float4 b4 = ((const float4*)bb)[tid];
    float4 o;
    o.x = (vv.x - mean) * rstd * gg.x + b4.x;
    o.y = (vv.y - mean) * rstd * gg.y + b4.y;
    o.z = (vv.z - mean) * rstd * gg.z + b4.z;
    o.w = (vv.w - mean) * rstd * gg.w + b4.w;
    out16[(size_t)n * (Cc / 4) + tid] = f4toh(o);
}

// ---------------- launcher ----------------
// BK=64, 3 stages
#define SM128_64 (3*(128*72*2 + 64*136*2))
#define SM32_64  (3*(32*72*2 + 64*72*2))

extern "C" void kernel_launch(void* const* d_in, const int* in_sizes, int n_in,
                              void* d_out, int out_size)
{
    (void)in_sizes; (void)n_in; (void)out_size;
    const float* x     = (const float*)d_in[0];
    const float* tmx   = (const float*)d_in[1];
    const float* tmw   = (const float*)d_in[2];
    const float* tmk   = (const float*)d_in[3];
    const float* tmv   = (const float*)d_in[4];
    const float* tmr   = (const float*)d_in[5];
    const float* w1    = (const float*)d_in[6];
    const float* w2    = (const float*)d_in[7];
    const float* tdec  = (const float*)d_in[8];
    const float* dw1   = (const float*)d_in[9];
    const float* dw2   = (const float*)d_in[10];
    const float* faaaa = (const float*)d_in[11];
    const float* Wr    = (const float*)d_in[12];
    const float* Wk    = (const float*)d_in[13];
    const float* Wv    = (const float*)d_in[14];
    const float* Wo    = (const float*)d_in[15];
    const float* lng   = (const float*)d_in[16];
    const float* lnb   = (const float*)d_in[17];
    float* out = (float*)d_out;

    static float *p_y = nullptr, *p_we, *p_ss, *p_wp;
    static __half *p16_yn, *p16_xw, *p16_xk, *p16_xv, *p16_xr,
                  *p16_r, *p16_k, *p16_v, *p16_h, *p16_t1,
                  *p16_wr, *p16_wk, *p16_wv, *p16_wo, *p16_w1, *p16_dw1, *p16_dw2, *p16_w2;
    if (!p_y) {
        cudaGetSymbolAddress((void**)&p_y,     g_y);
        cudaGetSymbolAddress((void**)&p_we,    g_we);
        cudaGetSymbolAddress((void**)&p_ss,    g_sseg);
        cudaGetSymbolAddress((void**)&p_wp,    g_wp);
        cudaGetSymbolAddress((void**)&p16_yn,  g16_yn);
        cudaGetSymbolAddress((void**)&p16_xw,  g16_xw);
        cudaGetSymbolAddress((void**)&p16_xk,  g16_xk);
        cudaGetSymbolAddress((void**)&p16_xv,  g16_xv);
        cudaGetSymbolAddress((void**)&p16_xr,  g16_xr);
        cudaGetSymbolAddress((void**)&p16_r,   g16_r);
        cudaGetSymbolAddress((void**)&p16_k,   g16_k);
        cudaGetSymbolAddress((void**)&p16_v,   g16_v);
        cudaGetSymbolAddress((void**)&p16_h,   g16_h);
        cudaGetSymbolAddress((void**)&p16_t1,  g16_t1);
        cudaGetSymbolAddress((void**)&p16_wr,  g16_wr);
        cudaGetSymbolAddress((void**)&p16_wk,  g16_wk);
        cudaGetSymbolAddress((void**)&p16_wv,  g16_wv);
        cudaGetSymbolAddress((void**)&p16_wo,  g16_wo);
        cudaGetSymbolAddress((void**)&p16_w1,  g16_w1);
        cudaGetSymbolAddress((void**)&p16_dw1, g16_dw1);
        cudaGetSymbolAddress((void**)&p16_dw2, g16_dw2);
        cudaGetSymbolAddress((void**)&p16_w2,  g16_w2);
        cudaFuncSetAttribute(gemmh<128,128,EPI_NONE,0>, cudaFuncAttributeMaxDynamicSharedMemorySize, SM128_64);
        cudaFuncSetAttribute(gemmh<32,64,EPI_TANH,1>,   cudaFuncAttributeMaxDynamicSharedMemorySize, SM32_64);
        cudaFuncSetAttribute(gemmh_batch, cudaFuncAttributeMaxDynamicSharedMemorySize, SM128_64);
        cudaFuncSetAttribute(k_mix, cudaFuncAttributeMaxDynamicSharedMemorySize, MIX_SMEM);
    }

    // 0) weight converts — single launch, 8 segments (counts in float4)
    {
        CvtArgs a;
        const float* srcs[8] = { Wr, Wk, Wv, Wo, w1, dw1, dw2, w2 };
        __half* dsts[8] = { p16_wr, p16_wk, p16_wv, p16_wo, p16_w1, p16_dw1, p16_dw2, p16_w2 };
        int cnts[8] = { Cc*Cc/4, Cc*Cc/4, Cc*Cc/4, Cc*Cc/4, Cc*DM4/4, Cc*DDEC/4, DDEC*Cc/4, 4*32*Cc/4 };
        int cum = 0;
        for (int i = 0; i < 8; i++) {
            a.s[i] = (const float4*)srcs[i];
            a.d[i] = (uint2*)dsts[i];
            a.off[i] = cum;
            cum += cnts[i];
        }
        a.off[8] = cum;
        k_cvt<<<(cum + 255) / 256, 256>>>(a);
    }

    // 1) fused shift + h-GEMM: h = tanh(xxx @ w1), xxx built on the fly
    k_hshift<<<dim3(NTOK/64, DM4/64), 256>>>(x, tmx, p16_w1, p16_h);

    // 2) fused mix: xw/xk/xv/xr (xx computed inline from x)
    k_mix<<<dim3(NTOK/64, Cc/64), 256, MIX_SMEM>>>(
        p16_h, p16_w2, x, tmw, tmk, tmv, tmr,
        p16_xw, p16_xk, p16_xv, p16_xr);

    // 3) t1 = tanh(xw @ dw1)  — BM=32 tiles: 256 CTAs
    gemmh<32,64,EPI_TANH,1><<<dim3(NTOK/32, 1), 256, SM32_64>>>(
        p16_xw, p16_dw1, p16_t1, Cc/64, Cc, DDEC, DDEC, nullptr);

    // 4) batched: r/k/v projections (fp16 out) + wexp
    {
        BatchArgs ba;
        ba.A[0] = p16_xr; ba.B[0] = p16_wr; ba.C[0] = p16_r; ba.nT[0] = Cc/64; ba.lda[0] = Cc;
        ba.A[1] = p16_xk; ba.B[1] = p16_wk; ba.C[1] = p16_k; ba.nT[1] = Cc/64; ba.lda[1] = Cc;
        ba.A[2] = p16_xv; ba.B[2] = p16_wv; ba.C[2] = p16_v; ba.nT[2] = Cc/64; ba.lda[2] = Cc;
        ba.A[3] = p16_t1; ba.B[3] = p16_dw2; ba.C[3] = p_we; ba.nT[3] = DDEC/64; ba.lda[3] = DDEC;
        ba.bias = tdec;
        gemmh_batch<<<dim3(NTOK/128, Cc/128, 4), 256, SM128_64>>>(ba);
    }

    // 5) WKV6 chunked scan (scan fused into pass 2)
    k_wkv1<<<dim3(P_SEG, Bc * Hc), 64>>>(p16_k, p16_v, p_we, p_ss, p_wp);
    k_wkv2<<<dim3(P_SEG, Bc * Hc), 64>>>(faaaa, p16_r, p16_k, p16_v, p_we, p_ss, p_wp, p_y);

    // 6) LayerNorm -> fp16
    k_ln<<<NTOK, 256>>>(p_y, lng, lnb, (uint2*)p16_yn);

    // 7) out = yn @ Wo  — 128x128 tiles (revert: lower L2 traffic wins)
    gemmh<128,128,EPI_NONE,0><<<dim3(NTOK/128, Cc/128), 256, SM128_64>>>(
        p16_yn, p16_wo, out, Cc/64, Cc, Cc, Cc, nullptr);
}